// round 11
// baseline (speedup 1.0000x reference)
#include <cuda_runtime.h>
#include <cstdint>

#define CN    8192
#define NB    4096
#define CAP   16
#define OVCAP 512
#define K1B   64
#define K1T   128
#define K2B   16
#define K2T   512

// All state is zero at module load; K2's last block restores it to zero
// after every call (self-cleaning), so no zeroing kernel is needed.
__device__ int      g_cnt[NB];
__device__ float    g_bsum[NB];
__device__ float2   g_slot[NB * CAP];   // one bucket = 128B = one cache line
__device__ float2   g_ovf[OVCAP];
__device__ int      g_ovf_cnt;
__device__ unsigned g_done;
__device__ unsigned g_k1done;

__device__ __forceinline__ void arrive_release(unsigned* p) {
    asm volatile("red.release.gpu.global.add.u32 [%0], %1;"
                 :: "l"(p), "r"(1u) : "memory");
}
__device__ __forceinline__ unsigned ld_acquire(const unsigned* p) {
    unsigned v;
    asm volatile("ld.acquire.gpu.global.u32 %0, [%1];"
                 : "=r"(v) : "l"(p) : "memory");
    return v;
}

// Monotone bucket map: b_j > b_i => sv_j > sv_i ; b_j < b_i => sv_j < sv_i.
__device__ __forceinline__ int bkt(float v) {
    float x = v * (float)NB;
    x = fminf(fmaxf(x, 0.0f), (float)(NB - 1));
    return (int)x;
}

// ---- K1: exp + bucket insert (state guaranteed zero at entry) ----
__global__ void __launch_bounds__(K1T) k1_insert(
    const float* __restrict__ theta,
    const float* __restrict__ sv,
    float* __restrict__ out)
{
    // Let the dependent kernel start launching immediately.
    cudaTriggerProgrammaticLaunchCompletion();

    int i = blockIdx.x * K1T + threadIdx.x;       // 0..8191
    if (i == 0) out[0] = 0.0f;                    // K2 accumulates into out
    float v = sv[i];
    float e = __expf(theta[i]);
    int b = bkt(v);
    int p = atomicAdd(&g_cnt[b], 1);
    atomicAdd(&g_bsum[b], e);                     // REDG (result unused)
    if (p < CAP) {
        g_slot[b * CAP + p] = make_float2(v, e);
    } else {
        int q = atomicAdd(&g_ovf_cnt, 1);         // robustness path (expected 0)
        if (q < OVCAP) g_ovf[q] = make_float2(v, e);
    }

    // Block-level release arrival: K2 proceeds as soon as data is in L2,
    // without waiting for this kernel's completion/teardown signal.
    __syncthreads();
    if (threadIdx.x == 0) arrive_release(&g_k1done);
}

// ---- K2: suffix scan + per-row compute + last-block cleanup ----
__global__ void __launch_bounds__(K2T) k2_compute(
    const float* __restrict__ theta,
    const float* __restrict__ sv,
    const float* __restrict__ cen,
    float* __restrict__ out)
{
    __shared__ float s_suf[NB + 1];
    __shared__ float s_w[16];
    __shared__ int   s_last;

    const int t    = threadIdx.x;
    const int lane = t & 31;
    const int wid  = t >> 5;

    // ---- pre-sync phase: inputs K1 does not write (overlaps K1 via PDL) ----
    const int   r  = blockIdx.x * K2T + t;        // 0..8191
    const float v  = sv[r];
    const float th = theta[r];
    const float ce = cen[r];
    const int   b  = bkt(v);
    if (t == 0) s_last = 0;

    // ---- wait for K1's data (release/acquire flag, not kernel completion) ----
    if (t == 0) {
        while (ld_acquire(&g_k1done) < K1B) { }
    }
    __syncthreads();   // acquire result broadcast to the block

    // ---- prefetch row-local K1 outputs; complete under the scan below ----
    const int cnt_raw = g_cnt[b];
    const float4* sl4 = reinterpret_cast<const float4*>(&g_slot[b * CAP]);
    const float4 sA = sl4[0];                     // slots 0,1
    const float4 sB = sl4[1];                     // slots 2,3
    const int ovl_raw = g_ovf_cnt;

    // ---- suffix scan over 4096 bucket sums (each thread owns 8, reversed) --
    const int c = (K2T - 1) - t;                  // chunk index, reversed order
    float g[8];
    {
        const float4* bs4 = reinterpret_cast<const float4*>(g_bsum);
        float4 f0 = bs4[c * 2 + 0];
        float4 f1 = bs4[c * 2 + 1];
        g[0] = f0.x; g[1] = f0.y; g[2] = f0.z; g[3] = f0.w;
        g[4] = f1.x; g[5] = f1.y; g[6] = f1.z; g[7] = f1.w;
    }
    float gs = g[0] + g[1] + g[2] + g[3] + g[4] + g[5] + g[6] + g[7];

    float val = gs;                               // inclusive scan (t asc = suffix)
    #pragma unroll
    for (int o = 1; o < 32; o <<= 1) {
        float n = __shfl_up_sync(0xffffffffu, val, o);
        if (lane >= o) val += n;
    }
    if (lane == 31) s_w[wid] = val;
    __syncthreads();
    if (t < 16) {
        float wv = s_w[t];
        #pragma unroll
        for (int o = 1; o < 16; o <<= 1) {
            float n = __shfl_up_sync(0x0000ffffu, wv, o);
            if (t >= o) wv += n;
        }
        s_w[t] = wv;
    }
    __syncthreads();
    val += (wid > 0) ? s_w[wid - 1] : 0.0f;       // suffix INCLUDING own chunk

    float run = val - gs;                         // suffix of strictly-later chunks
    #pragma unroll
    for (int i = 7; i >= 0; i--) {
        run += g[i];
        s_suf[c * 8 + i] = run;                   // suffix including bucket c*8+i
    }
    if (t == 0) s_suf[NB] = 0.0f;
    __syncthreads();

    // ---- combine: same-bucket exact part (prefetched) + suffix ----
    const int cnt = cnt_raw < CAP ? cnt_raw : CAP;
    float w = 0.0f;
    if (cnt > 0 && sA.x >= v) w += sA.y;
    if (cnt > 1 && sA.z >= v) w += sA.w;
    if (cnt > 2 && sB.x >= v) w += sB.y;
    if (cnt > 3 && sB.z >= v) w += sB.w;
    const float2* sl = &g_slot[b * CAP];
    for (int m = 4; m < cnt; m++) {               // rare (P ≈ 5%)
        float2 s = sl[m];
        if (s.x >= v) w += s.y;
    }
    int L = ovl_raw < OVCAP ? ovl_raw : OVCAP;    // expected 0
    for (int m = 0; m < L; m++) {
        float2 s = g_ovf[m];
        if (s.x >= v) w += s.y;
    }

    float risk = s_suf[b + 1] + w;
    float acc  = (th - __logf(risk)) * ce;

    // ---- block reduce, then atomic straight into out ----
    #pragma unroll
    for (int o = 16; o > 0; o >>= 1) acc += __shfl_xor_sync(0xffffffffu, acc, o);
    if (lane == 0) s_w[wid] = acc;
    __syncthreads();
    if (t == 0) {
        float p = 0.0f;
        #pragma unroll
        for (int q = 0; q < 16; q++) p += s_w[q];
        atomicAdd(out, -p / (float)CN);           // final value lands with last add
        __threadfence();                          // order reads/adds before done count
        unsigned old = atomicAdd(&g_done, 1u);
        if (old == K2B - 1) s_last = 1;           // all blocks done reading state
    }
    __syncthreads();

    // ---- last block: restore all state to zero (self-cleaning) ----
    if (s_last) {
        if (t == 0) { g_ovf_cnt = 0; g_done = 0u; g_k1done = 0u; }
        #pragma unroll
        for (int i = 0; i < NB / K2T; i++) {      // 8 each
            g_cnt [t + i * K2T] = 0;
            g_bsum[t + i * K2T] = 0.0f;
        }
    }
}

extern "C" void kernel_launch(void* const* d_in, const int* in_sizes, int n_in,
                              void* d_out, int out_size) {
    const float* hazard_pred = (const float*)d_in[0];
    const float* survtime    = (const float*)d_in[1];
    const float* censor      = (const float*)d_in[2];
    float* out = (float*)d_out;

    k1_insert<<<K1B, K1T>>>(hazard_pred, survtime, out);

    // K2 launched with Programmatic Stream Serialization so it becomes
    // resident while K1 runs; actual data dependency is the software flag.
    cudaLaunchConfig_t cfg = {};
    cfg.gridDim  = dim3(K2B);
    cfg.blockDim = dim3(K2T);
    cfg.dynamicSmemBytes = 0;
    cfg.stream = 0;
    cudaLaunchAttribute attrs[1];
    attrs[0].id = cudaLaunchAttributeProgrammaticStreamSerialization;
    attrs[0].val.programmaticStreamSerializationAllowed = 1;
    cfg.attrs = attrs;
    cfg.numAttrs = 1;
    cudaLaunchKernelEx(&cfg, k2_compute, hazard_pred, survtime, censor, out);
}

// round 12
// speedup vs baseline: 1.0269x; 1.0269x over previous
#include <cuda_runtime.h>
#include <cstdint>

#define CN    8192
#define NB    4096
#define CAP   16
#define OVCAP 512
#define NBLK  16
#define NTHR  512

// All state is zero at module load; the last block restores it to zero
// after every call (self-cleaning), so no zeroing pass is needed.
__device__ int      g_cnt[NB];
__device__ float    g_bsum[NB];
__device__ float2   g_slot[NB * CAP];   // one bucket = 128B = one cache line
__device__ float2   g_ovf[OVCAP];
__device__ int      g_ovf_cnt;
__device__ unsigned g_done;
__device__ unsigned g_flag;

__device__ __forceinline__ void arrive_release(unsigned* p) {
    asm volatile("red.release.gpu.global.add.u32 [%0], %1;"
                 :: "l"(p), "r"(1u) : "memory");
}
__device__ __forceinline__ unsigned ld_acquire(const unsigned* p) {
    unsigned v;
    asm volatile("ld.acquire.gpu.global.u32 %0, [%1];"
                 : "=r"(v) : "l"(p) : "memory");
    return v;
}
__device__ __forceinline__ void fence_acqrel_gpu() {
    asm volatile("fence.acq_rel.gpu;" ::: "memory");
}

// Monotone bucket map: b_j > b_i => sv_j > sv_i ; b_j < b_i => sv_j < sv_i.
__device__ __forceinline__ int bkt(float v) {
    float x = v * (float)NB;
    x = fminf(fmaxf(x, 0.0f), (float)(NB - 1));
    return (int)x;
}

__global__ void __launch_bounds__(NTHR) cox_fused(
    const float* __restrict__ theta,
    const float* __restrict__ sv,
    const float* __restrict__ cen,
    float* __restrict__ out)
{
    __shared__ float s_suf[NB + 1];
    __shared__ float s_w[16];
    __shared__ int   s_last;

    const int t    = threadIdx.x;
    const int lane = t & 31;
    const int wid  = t >> 5;
    const int gid  = blockIdx.x * NTHR + t;       // 0..8191, one element/thread

    // ---- Phase A: load own element once, exp, bucket insert ----
    const float v  = sv[gid];
    const float th = theta[gid];
    const float ce = cen[gid];
    const float e  = __expf(th);
    const int   b  = bkt(v);

    if (gid == 0) out[0] = 0.0f;                  // accumulated below, post-barrier
    if (t == 0)  s_last = 0;

    int p = atomicAdd(&g_cnt[b], 1);
    atomicAdd(&g_bsum[b], e);                     // REDG, result unused
    if (p < CAP) {
        g_slot[b * CAP + p] = make_float2(v, e);
    } else {
        int q = atomicAdd(&g_ovf_cnt, 1);         // robustness path (expected 0)
        if (q < OVCAP) g_ovf[q] = make_float2(v, e);
    }

    // ---- software global barrier (release/acquire, 16 symmetric blocks) ----
    __syncthreads();                              // all block inserts issued
    if (t == 0) {
        arrive_release(&g_flag);
        while (ld_acquire(&g_flag) < NBLK) { }
    }
    __syncthreads();
    fence_acqrel_gpu();                           // make peer stores visible to all threads

    // ---- prefetch row-local state; completes under the scan below ----
    const int cnt_raw = g_cnt[b];
    const float4* sl4 = reinterpret_cast<const float4*>(&g_slot[b * CAP]);
    const float4 sA = sl4[0];                     // slots 0,1
    const float4 sB = sl4[1];                     // slots 2,3
    const int ovl_raw = g_ovf_cnt;

    // ---- suffix scan over 4096 bucket sums (each thread owns 8, reversed) --
    const int c = (NTHR - 1) - t;                 // chunk index, reversed order
    float g[8];
    {
        const float4* bs4 = reinterpret_cast<const float4*>(g_bsum);
        float4 f0 = bs4[c * 2 + 0];
        float4 f1 = bs4[c * 2 + 1];
        g[0] = f0.x; g[1] = f0.y; g[2] = f0.z; g[3] = f0.w;
        g[4] = f1.x; g[5] = f1.y; g[6] = f1.z; g[7] = f1.w;
    }
    float gs = g[0] + g[1] + g[2] + g[3] + g[4] + g[5] + g[6] + g[7];

    float val = gs;                               // inclusive scan (t asc = suffix)
    #pragma unroll
    for (int o = 1; o < 32; o <<= 1) {
        float n = __shfl_up_sync(0xffffffffu, val, o);
        if (lane >= o) val += n;
    }
    if (lane == 31) s_w[wid] = val;
    __syncthreads();
    if (t < 16) {
        float wv = s_w[t];
        #pragma unroll
        for (int o = 1; o < 16; o <<= 1) {
            float n = __shfl_up_sync(0x0000ffffu, wv, o);
            if (t >= o) wv += n;
        }
        s_w[t] = wv;
    }
    __syncthreads();
    val += (wid > 0) ? s_w[wid - 1] : 0.0f;       // suffix INCLUDING own chunk

    float run = val - gs;                         // suffix of strictly-later chunks
    #pragma unroll
    for (int i = 7; i >= 0; i--) {
        run += g[i];
        s_suf[c * 8 + i] = run;                   // suffix including bucket c*8+i
    }
    if (t == 0) s_suf[NB] = 0.0f;
    __syncthreads();

    // ---- combine: same-bucket exact part (prefetched) + suffix ----
    const int cnt = cnt_raw < CAP ? cnt_raw : CAP;
    float w = 0.0f;
    if (cnt > 0 && sA.x >= v) w += sA.y;
    if (cnt > 1 && sA.z >= v) w += sA.w;
    if (cnt > 2 && sB.x >= v) w += sB.y;
    if (cnt > 3 && sB.z >= v) w += sB.w;
    const float2* sl = &g_slot[b * CAP];
    for (int m = 4; m < cnt; m++) {               // rare (P ≈ 5%)
        float2 s = sl[m];
        if (s.x >= v) w += s.y;
    }
    int L = ovl_raw < OVCAP ? ovl_raw : OVCAP;    // expected 0
    for (int m = 0; m < L; m++) {
        float2 s = g_ovf[m];
        if (s.x >= v) w += s.y;
    }

    float risk = s_suf[b + 1] + w;
    float acc  = (th - __logf(risk)) * ce;

    // ---- block reduce, then atomic straight into out ----
    #pragma unroll
    for (int o = 16; o > 0; o >>= 1) acc += __shfl_xor_sync(0xffffffffu, acc, o);
    if (lane == 0) s_w[wid] = acc;
    __syncthreads();
    if (t == 0) {
        float ps = 0.0f;
        #pragma unroll
        for (int q = 0; q < 16; q++) ps += s_w[q];
        atomicAdd(out, -ps / (float)CN);          // final value lands with last add
        __threadfence();                          // order reads/adds before done count
        unsigned old = atomicAdd(&g_done, 1u);
        if (old == NBLK - 1) s_last = 1;          // all blocks done reading state
    }
    __syncthreads();

    // ---- last block: restore all state to zero (self-cleaning) ----
    if (s_last) {
        if (t == 0) { g_ovf_cnt = 0; g_done = 0u; g_flag = 0u; }
        #pragma unroll
        for (int i = 0; i < NB / NTHR; i++) {     // 8 each
            g_cnt [t + i * NTHR] = 0;
            g_bsum[t + i * NTHR] = 0.0f;
        }
    }
}

extern "C" void kernel_launch(void* const* d_in, const int* in_sizes, int n_in,
                              void* d_out, int out_size) {
    const float* hazard_pred = (const float*)d_in[0];
    const float* survtime    = (const float*)d_in[1];
    const float* censor      = (const float*)d_in[2];
    float* out = (float*)d_out;

    cox_fused<<<NBLK, NTHR>>>(hazard_pred, survtime, censor, out);
}